// round 8
// baseline (speedup 1.0000x reference)
#include <cuda_runtime.h>
#include <cuda_bf16.h>
#include <math.h>

// Problem dims (fixed by reference setup_inputs)
constexpr int Bc = 32;
constexpr int Tc = 4;
constexpr int Lc = 196;
constexpr int Dc = 384;
constexpr int Hc = 1536;
constexpr int Mrows = Tc * Bc * Lc;   // 25088

// Scratch (device globals; allocation-free per harness rules)
__device__ float g_h1[(size_t)Mrows * Hc];   // pre-LN GEMM1 output  (~154 MB)
__device__ float g_s1[(size_t)Mrows * Hc];   // spikes layer 1       (~154 MB)
__device__ float g_h2[(size_t)Mrows * Dc];   // pre-LN GEMM2 output  (~38 MB)

// ---------------------------------------------------------------------------
// GEMM core (R5 config — proven): 128x128 tile, BK=8, 256 threads, 8x8 per
// thread (split 4+4, conflict-free), double-buffered, 1 sync/iter.
// Bit-exactness contract: each output element is ONE fp32 FMA chain with k
// strictly ascending 0..K-1 (matches the reference einsum), bias added as a
// single separate __fadd_rn at the end.
// blockIdx.x = N-block (small), blockIdx.y = M-block  -> consecutive CTAs
// share the A block and the whole weight matrix through L2.
// Smem rows padded 128->132 floats (132 % 32 == 4) -> conflict-free STS.
// ---------------------------------------------------------------------------
#define GEMM_BODY(K_DIM, APTR_EXPR, BPTR_EXPR, BIAS, OUTBASE, OUT_LD)          \
    constexpr int BK = 8;                                                      \
    constexpr int LDS_ = 132;                                                  \
    __shared__ float As[2][BK][LDS_];                                          \
    __shared__ float Bs[2][BK][LDS_];                                          \
    const int tid = threadIdx.x;                                               \
    const int lr = tid >> 1;                                                   \
    const int lc = (tid & 1) * 4;                                              \
    const float* aptr = (APTR_EXPR);                                           \
    const float* bptr = (BPTR_EXPR);                                           \
    const int tx = tid & 15;                                                   \
    const int ty = tid >> 4;                                                   \
    float acc[8][8] = {};                                                      \
    float4 av = *(const float4*)aptr;                                          \
    float4 bv = *(const float4*)bptr;                                          \
    int buf = 0;                                                               \
    As[0][lc + 0][lr] = av.x; As[0][lc + 1][lr] = av.y;                        \
    As[0][lc + 2][lr] = av.z; As[0][lc + 3][lr] = av.w;                        \
    Bs[0][lc + 0][lr] = bv.x; Bs[0][lc + 1][lr] = bv.y;                        \
    Bs[0][lc + 2][lr] = bv.z; Bs[0][lc + 3][lr] = bv.w;                        \
    __syncthreads();                                                           \
    for (int k0 = BK; k0 < (K_DIM) + BK; k0 += BK) {                           \
        const bool more = (k0 < (K_DIM));                                      \
        if (more) {                                                            \
            av = *(const float4*)(aptr + k0);                                  \
            bv = *(const float4*)(bptr + k0);                                  \
        }                                                                      \
        _Pragma("unroll")                                                      \
        for (int k = 0; k < BK; k++) {                                         \
            const float4 a0 = *(const float4*)&As[buf][k][ty * 4];             \
            const float4 a1 = *(const float4*)&As[buf][k][64 + ty * 4];        \
            const float4 b0 = *(const float4*)&Bs[buf][k][tx * 4];             \
            const float4 b1 = *(const float4*)&Bs[buf][k][64 + tx * 4];        \
            const float am[8] = {a0.x, a0.y, a0.z, a0.w, a1.x, a1.y, a1.z, a1.w}; \
            const float bn[8] = {b0.x, b0.y, b0.z, b0.w, b1.x, b1.y, b1.z, b1.w}; \
            _Pragma("unroll")                                                  \
            for (int i = 0; i < 8; i++) {                                      \
                _Pragma("unroll")                                              \
                for (int j = 0; j < 8; j++)                                    \
                    acc[i][j] = __fmaf_rn(am[i], bn[j], acc[i][j]);            \
            }                                                                  \
        }                                                                      \
        if (more) {                                                            \
            buf ^= 1;                                                          \
            As[buf][lc + 0][lr] = av.x; As[buf][lc + 1][lr] = av.y;            \
            As[buf][lc + 2][lr] = av.z; As[buf][lc + 3][lr] = av.w;            \
            Bs[buf][lc + 0][lr] = bv.x; Bs[buf][lc + 1][lr] = bv.y;            \
            Bs[buf][lc + 2][lr] = bv.z; Bs[buf][lc + 3][lr] = bv.w;            \
            __syncthreads();                                                   \
        }                                                                      \
    }                                                                          \
    const int n_base = blockIdx.x * 128;                                       \
    const int m_base = blockIdx.y * 128;                                       \
    const float4 bb0 = *(const float4*)((BIAS) + n_base + tx * 4);             \
    const float4 bb1 = *(const float4*)((BIAS) + n_base + 64 + tx * 4);        \
    _Pragma("unroll")                                                          \
    for (int i = 0; i < 8; i++) {                                              \
        const int m = m_base + ((i < 4) ? (ty * 4 + i) : (64 + ty * 4 + i - 4)); \
        float* o = (OUTBASE) + (size_t)m * (OUT_LD) + n_base;                  \
        float4 o0, o1;                                                         \
        o0.x = __fadd_rn(acc[i][0], bb0.x); o0.y = __fadd_rn(acc[i][1], bb0.y);\
        o0.z = __fadd_rn(acc[i][2], bb0.z); o0.w = __fadd_rn(acc[i][3], bb0.w);\
        o1.x = __fadd_rn(acc[i][4], bb1.x); o1.y = __fadd_rn(acc[i][5], bb1.y);\
        o1.z = __fadd_rn(acc[i][6], bb1.z); o1.w = __fadd_rn(acc[i][7], bb1.w);\
        *(float4*)(o + tx * 4) = o0;                                           \
        *(float4*)(o + 64 + tx * 4) = o1;                                      \
    }

__global__ __launch_bounds__(256) void gemm1_kernel(
    const float* __restrict__ x, const float* __restrict__ W1,
    const float* __restrict__ b1) {
    // A row r = (t*B + b)*L + l maps into x at ((b*T + t)*L + l)*D
    const int r_ = blockIdx.y * 128 + (threadIdx.x >> 1);
    const int l_  = r_ % Lc;
    const int tb_ = r_ / Lc;
    const int bI_ = tb_ % Bc;
    const int tI_ = tb_ / Bc;
    GEMM_BODY(Dc,
              x  + (size_t)((bI_ * Tc + tI_) * Lc + l_) * Dc + ((threadIdx.x & 1) * 4),
              W1 + (size_t)(blockIdx.x * 128 + (threadIdx.x >> 1)) * Dc + ((threadIdx.x & 1) * 4),
              b1, g_h1, Hc)
}

__global__ __launch_bounds__(256) void gemm2_kernel(
    const float* __restrict__ W2, const float* __restrict__ b2) {
    GEMM_BODY(Hc,
              g_s1 + (size_t)(blockIdx.y * 128 + (threadIdx.x >> 1)) * Hc + ((threadIdx.x & 1) * 4),
              W2   + (size_t)(blockIdx.x * 128 + (threadIdx.x >> 1)) * Hc + ((threadIdx.x & 1) * 4),
              b2, g_h2, Dc)
}

// ---------------------------------------------------------------------------
// Exact pairwise f32->f64 sums (order-noise ~1e-16, irrelevant to f32 result).
// ---------------------------------------------------------------------------
__device__ __forceinline__ double pair4(const float4& y) {
    return ((double)y.x + (double)y.y) + ((double)y.z + (double)y.w);
}
__device__ __forceinline__ double pair4sq(const float4& y, float mu) {
    const float dx = __fsub_rn(y.x, mu), dy = __fsub_rn(y.y, mu);
    const float dz = __fsub_rn(y.z, mu), dw = __fsub_rn(y.w, mu);
    return ((double)__fmul_rn(dx, dx) + (double)__fmul_rn(dy, dy)) +
           ((double)__fmul_rn(dz, dz) + (double)__fmul_rn(dw, dw));
}

// Elementwise LIF step, bit-exact op sequence (no contraction):
#define LIF_E(Y, G, B, V, S, MU, RS)                                           \
    {                                                                          \
        const float yy = __fadd_rn(                                            \
            __fmul_rn(__fmul_rn(__fsub_rn((Y), (MU)), (RS)), (G)), (B));       \
        (V) = __fadd_rn((V), __fmul_rn(__fsub_rn(yy, (V)), 0.5f));             \
        (S) = ((V) >= 1.0f) ? 1.f : 0.f;                                       \
        (V) = __fmul_rn((V), __fsub_rn(1.0f, (S)));                            \
    }

// ---------------------------------------------------------------------------
// Batched block reduce of Tc doubles, 192 threads (6 warps). After the two
// syncs every thread computes the same deterministic pairwise sum from smem.
// ---------------------------------------------------------------------------
__device__ __forceinline__ void block_reduce_t4_192(double* a) {
    __shared__ double sh[Tc][6];
    const unsigned m = 0xffffffffu;
#pragma unroll
    for (int o = 16; o; o >>= 1) {
#pragma unroll
        for (int t = 0; t < Tc; t++) a[t] += __shfl_xor_sync(m, a[t], o);
    }
    const int lane = threadIdx.x & 31, w = threadIdx.x >> 5;
    __syncthreads();               // previous users of sh are done
    if (lane == 0) {
#pragma unroll
        for (int t = 0; t < Tc; t++) sh[t][w] = a[t];
    }
    __syncthreads();
#pragma unroll
    for (int t = 0; t < Tc; t++)
        a[t] = ((sh[t][0] + sh[t][1]) + (sh[t][2] + sh[t][3])) +
               (sh[t][4] + sh[t][5]);
}

// ---------------------------------------------------------------------------
// Layer-1 LN+LIF: one 192-thread block per (b,l) row (H=1536 = 192*8).
// All Tc timestep rows loaded up front (MLP=8), stats batched across t,
// then the serial LIF recurrence in registers.
// ---------------------------------------------------------------------------
__global__ __launch_bounds__(192) void ln_lif1_kernel(
    const float* __restrict__ src, const float* __restrict__ gamma,
    const float* __restrict__ beta, float* __restrict__ dst) {
    const int bl = blockIdx.x;               // (b,l)
    const int bI = bl / Lc, l = bl % Lc;
    const int c0 = threadIdx.x * 4;
    const int c1 = c0 + 768;
    const int rbase = bI * Lc + l;

    float4 y0[Tc], y1[Tc];
#pragma unroll
    for (int t = 0; t < Tc; t++) {
        const float* p = src + (size_t)(t * (Bc * Lc) + rbase) * Hc;
        y0[t] = *(const float4*)(p + c0);
        y1[t] = *(const float4*)(p + c1);
    }

    double s[Tc];
#pragma unroll
    for (int t = 0; t < Tc; t++) s[t] = pair4(y0[t]) + pair4(y1[t]);
    block_reduce_t4_192(s);
    float mu[Tc];
#pragma unroll
    for (int t = 0; t < Tc; t++) mu[t] = (float)(s[t] / (double)Hc);

    double s2[Tc];
#pragma unroll
    for (int t = 0; t < Tc; t++)
        s2[t] = pair4sq(y0[t], mu[t]) + pair4sq(y1[t], mu[t]);
    block_reduce_t4_192(s2);
    float rs[Tc];
#pragma unroll
    for (int t = 0; t < Tc; t++) {
        const float var = (float)(s2[t] / (double)Hc);
        rs[t] = __fdiv_rn(1.0f, __fsqrt_rn(__fadd_rn(var, 1e-5f)));
    }

    const float4 gg0 = *(const float4*)(gamma + c0);
    const float4 gg1 = *(const float4*)(gamma + c1);
    const float4 bb0 = *(const float4*)(beta + c0);
    const float4 bb1 = *(const float4*)(beta + c1);
    float4 v0 = make_float4(0.f, 0.f, 0.f, 0.f);
    float4 v1 = make_float4(0.f, 0.f, 0.f, 0.f);
#pragma unroll
    for (int t = 0; t < Tc; t++) {
        float4 sp0, sp1;
        LIF_E(y0[t].x, gg0.x, bb0.x, v0.x, sp0.x, mu[t], rs[t])
        LIF_E(y0[t].y, gg0.y, bb0.y, v0.y, sp0.y, mu[t], rs[t])
        LIF_E(y0[t].z, gg0.z, bb0.z, v0.z, sp0.z, mu[t], rs[t])
        LIF_E(y0[t].w, gg0.w, bb0.w, v0.w, sp0.w, mu[t], rs[t])
        LIF_E(y1[t].x, gg1.x, bb1.x, v1.x, sp1.x, mu[t], rs[t])
        LIF_E(y1[t].y, gg1.y, bb1.y, v1.y, sp1.y, mu[t], rs[t])
        LIF_E(y1[t].z, gg1.z, bb1.z, v1.z, sp1.z, mu[t], rs[t])
        LIF_E(y1[t].w, gg1.w, bb1.w, v1.w, sp1.w, mu[t], rs[t])
        float* q = dst + (size_t)(t * (Bc * Lc) + rbase) * Hc;
        *(float4*)(q + c0) = sp0;
        *(float4*)(q + c1) = sp1;
    }
}

// ---------------------------------------------------------------------------
// Layer-2 LN+LIF -> final output [B,T,L,D]. Warp per (b,l) row (D=384=32*12),
// all Tc rows loaded up front (MLP=12), batched interleaved warp reduces.
// ---------------------------------------------------------------------------
__global__ __launch_bounds__(256) void ln_lif2_kernel(
    const float* __restrict__ src, const float* __restrict__ gamma,
    const float* __restrict__ beta, float* __restrict__ dst) {
    constexpr int J = Dc / 128;              // 3 float4 per lane
    const int bl = blockIdx.x * 8 + (threadIdx.x >> 5);
    const int lane = threadIdx.x & 31;
    const int bI = bl / Lc, l = bl % Lc;
    const unsigned msk = 0xffffffffu;
    const int rbase = bI * Lc + l;

    float4 y[Tc][J];
#pragma unroll
    for (int t = 0; t < Tc; t++) {
        const float* p = src + (size_t)(t * (Bc * Lc) + rbase) * Dc;
#pragma unroll
        for (int j = 0; j < J; j++)
            y[t][j] = *(const float4*)(p + lane * 4 + j * 128);
    }

    double s[Tc];
#pragma unroll
    for (int t = 0; t < Tc; t++)
        s[t] = (pair4(y[t][0]) + pair4(y[t][1])) + pair4(y[t][2]);
#pragma unroll
    for (int o = 16; o; o >>= 1) {
#pragma unroll
        for (int t = 0; t < Tc; t++) s[t] += __shfl_xor_sync(msk, s[t], o);
    }
    float mu[Tc];
#pragma unroll
    for (int t = 0; t < Tc; t++) mu[t] = (float)(s[t] / (double)Dc);

    double s2[Tc];
#pragma unroll
    for (int t = 0; t < Tc; t++)
        s2[t] = (pair4sq(y[t][0], mu[t]) + pair4sq(y[t][1], mu[t])) +
                pair4sq(y[t][2], mu[t]);
#pragma unroll
    for (int o = 16; o; o >>= 1) {
#pragma unroll
        for (int t = 0; t < Tc; t++) s2[t] += __shfl_xor_sync(msk, s2[t], o);
    }
    float rs[Tc];
#pragma unroll
    for (int t = 0; t < Tc; t++) {
        const float var = (float)(s2[t] / (double)Dc);
        rs[t] = __fdiv_rn(1.0f, __fsqrt_rn(__fadd_rn(var, 1e-5f)));
    }

    float4 gg[J], bb[J], v[J];
#pragma unroll
    for (int j = 0; j < J; j++) {
        gg[j] = *(const float4*)(gamma + lane * 4 + j * 128);
        bb[j] = *(const float4*)(beta  + lane * 4 + j * 128);
        v[j] = make_float4(0.f, 0.f, 0.f, 0.f);
    }
#pragma unroll
    for (int t = 0; t < Tc; t++) {
        float* q = dst + (size_t)((bI * Tc + t) * Lc + l) * Dc;
#pragma unroll
        for (int j = 0; j < J; j++) {
            float4 sp;
            LIF_E(y[t][j].x, gg[j].x, bb[j].x, v[j].x, sp.x, mu[t], rs[t])
            LIF_E(y[t][j].y, gg[j].y, bb[j].y, v[j].y, sp.y, mu[t], rs[t])
            LIF_E(y[t][j].z, gg[j].z, bb[j].z, v[j].z, sp.z, mu[t], rs[t])
            LIF_E(y[t][j].w, gg[j].w, bb[j].w, v[j].w, sp.w, mu[t], rs[t])
            *(float4*)(q + lane * 4 + j * 128) = sp;
        }
    }
}

// ---------------------------------------------------------------------------
extern "C" void kernel_launch(void* const* d_in, const int* in_sizes, int n_in,
                              void* d_out, int out_size) {
    const float* x   = (const float*)d_in[0];
    const float* W1  = (const float*)d_in[1];
    const float* b1  = (const float*)d_in[2];
    const float* g1  = (const float*)d_in[3];
    const float* be1 = (const float*)d_in[4];
    const float* W2  = (const float*)d_in[5];
    const float* b2  = (const float*)d_in[6];
    const float* g2  = (const float*)d_in[7];
    const float* be2 = (const float*)d_in[8];
    float* out = (float*)d_out;

    float *h1, *s1, *h2;
    cudaGetSymbolAddress((void**)&h1, g_h1);
    cudaGetSymbolAddress((void**)&s1, g_s1);
    cudaGetSymbolAddress((void**)&h2, g_h2);

    gemm1_kernel<<<dim3(Hc / 128, Mrows / 128), 256>>>(x, W1, b1);
    ln_lif1_kernel<<<Bc * Lc, 192>>>(h1, g1, be1, s1);
    gemm2_kernel<<<dim3(Dc / 128, Mrows / 128), 256>>>(W2, b2);
    ln_lif2_kernel<<<(Bc * Lc) / 8, 256>>>(h2, g2, be2, out);
}

// round 9
// speedup vs baseline: 1.1571x; 1.1571x over previous
#include <cuda_runtime.h>
#include <cuda_bf16.h>
#include <math.h>

// Problem dims (fixed by reference setup_inputs)
constexpr int Bc = 32;
constexpr int Tc = 4;
constexpr int Lc = 196;
constexpr int Dc = 384;
constexpr int Hc = 1536;
constexpr int Mrows = Tc * Bc * Lc;   // 25088

// Scratch (device globals; allocation-free per harness rules)
__device__ float g_h1[(size_t)Mrows * Hc];   // pre-LN GEMM1 output  (~154 MB)
__device__ float g_s1[(size_t)Mrows * Hc];   // spikes layer 1       (~154 MB)
__device__ float g_h2[(size_t)Mrows * Dc];   // pre-LN GEMM2 output  (~38 MB)
__device__ float g_mu1[Mrows], g_rs1[Mrows];
__device__ float g_mu2[Mrows], g_rs2[Mrows];

// ---------------------------------------------------------------------------
// GEMM core (R5 config — proven 1618us): 128x128 tile, BK=8, 256 threads,
// 8x8 per thread (split 4+4, conflict-free), double-buffered, 1 sync/iter.
// Bit-exactness contract: each output element is ONE fp32 FMA chain with k
// strictly ascending 0..K-1 (matches the reference einsum), bias added as a
// single separate __fadd_rn at the end.
// ---------------------------------------------------------------------------
#define GEMM_BODY(K_DIM, APTR_EXPR, BPTR_EXPR, BIAS, OUTBASE, OUT_LD)          \
    constexpr int BK = 8;                                                      \
    constexpr int LDS_ = 132;                                                  \
    __shared__ float As[2][BK][LDS_];                                          \
    __shared__ float Bs[2][BK][LDS_];                                          \
    const int tid = threadIdx.x;                                               \
    const int lr = tid >> 1;                                                   \
    const int lc = (tid & 1) * 4;                                              \
    const float* aptr = (APTR_EXPR);                                           \
    const float* bptr = (BPTR_EXPR);                                           \
    const int tx = tid & 15;                                                   \
    const int ty = tid >> 4;                                                   \
    float acc[8][8] = {};                                                      \
    float4 av = *(const float4*)aptr;                                          \
    float4 bv = *(const float4*)bptr;                                          \
    int buf = 0;                                                               \
    As[0][lc + 0][lr] = av.x; As[0][lc + 1][lr] = av.y;                        \
    As[0][lc + 2][lr] = av.z; As[0][lc + 3][lr] = av.w;                        \
    Bs[0][lc + 0][lr] = bv.x; Bs[0][lc + 1][lr] = bv.y;                        \
    Bs[0][lc + 2][lr] = bv.z; Bs[0][lc + 3][lr] = bv.w;                        \
    __syncthreads();                                                           \
    for (int k0 = BK; k0 < (K_DIM) + BK; k0 += BK) {                           \
        const bool more = (k0 < (K_DIM));                                      \
        if (more) {                                                            \
            av = *(const float4*)(aptr + k0);                                  \
            bv = *(const float4*)(bptr + k0);                                  \
        }                                                                      \
        _Pragma("unroll")                                                      \
        for (int k = 0; k < BK; k++) {                                         \
            const float4 a0 = *(const float4*)&As[buf][k][ty * 4];             \
            const float4 a1 = *(const float4*)&As[buf][k][64 + ty * 4];        \
            const float4 b0 = *(const float4*)&Bs[buf][k][tx * 4];             \
            const float4 b1 = *(const float4*)&Bs[buf][k][64 + tx * 4];        \
            const float am[8] = {a0.x, a0.y, a0.z, a0.w, a1.x, a1.y, a1.z, a1.w}; \
            const float bn[8] = {b0.x, b0.y, b0.z, b0.w, b1.x, b1.y, b1.z, b1.w}; \
            _Pragma("unroll")                                                  \
            for (int i = 0; i < 8; i++) {                                      \
                _Pragma("unroll")                                              \
                for (int j = 0; j < 8; j++)                                    \
                    acc[i][j] = __fmaf_rn(am[i], bn[j], acc[i][j]);            \
            }                                                                  \
        }                                                                      \
        if (more) {                                                            \
            buf ^= 1;                                                          \
            As[buf][lc + 0][lr] = av.x; As[buf][lc + 1][lr] = av.y;            \
            As[buf][lc + 2][lr] = av.z; As[buf][lc + 3][lr] = av.w;            \
            Bs[buf][lc + 0][lr] = bv.x; Bs[buf][lc + 1][lr] = bv.y;            \
            Bs[buf][lc + 2][lr] = bv.z; Bs[buf][lc + 3][lr] = bv.w;            \
            __syncthreads();                                                   \
        }                                                                      \
    }                                                                          \
    const int n_base = blockIdx.x * 128;                                       \
    const int m_base = blockIdx.y * 128;                                       \
    const float4 bb0 = *(const float4*)((BIAS) + n_base + tx * 4);             \
    const float4 bb1 = *(const float4*)((BIAS) + n_base + 64 + tx * 4);        \
    _Pragma("unroll")                                                          \
    for (int i = 0; i < 8; i++) {                                              \
        const int m = m_base + ((i < 4) ? (ty * 4 + i) : (64 + ty * 4 + i - 4)); \
        float* o = (OUTBASE) + (size_t)m * (OUT_LD) + n_base;                  \
        float4 o0, o1;                                                         \
        o0.x = __fadd_rn(acc[i][0], bb0.x); o0.y = __fadd_rn(acc[i][1], bb0.y);\
        o0.z = __fadd_rn(acc[i][2], bb0.z); o0.w = __fadd_rn(acc[i][3], bb0.w);\
        o1.x = __fadd_rn(acc[i][4], bb1.x); o1.y = __fadd_rn(acc[i][5], bb1.y);\
        o1.z = __fadd_rn(acc[i][6], bb1.z); o1.w = __fadd_rn(acc[i][7], bb1.w);\
        *(float4*)(o + tx * 4) = o0;                                           \
        *(float4*)(o + 64 + tx * 4) = o1;                                      \
    }

__global__ __launch_bounds__(256) void gemm1_kernel(
    const float* __restrict__ x, const float* __restrict__ W1,
    const float* __restrict__ b1) {
    // A row r = (t*B + b)*L + l maps into x at ((b*T + t)*L + l)*D
    const int r_ = blockIdx.y * 128 + (threadIdx.x >> 1);
    const int l_  = r_ % Lc;
    const int tb_ = r_ / Lc;
    const int bI_ = tb_ % Bc;
    const int tI_ = tb_ / Bc;
    GEMM_BODY(Dc,
              x  + (size_t)((bI_ * Tc + tI_) * Lc + l_) * Dc + ((threadIdx.x & 1) * 4),
              W1 + (size_t)(blockIdx.x * 128 + (threadIdx.x >> 1)) * Dc + ((threadIdx.x & 1) * 4),
              b1, g_h1, Hc)
}

__global__ __launch_bounds__(256) void gemm2_kernel(
    const float* __restrict__ W2, const float* __restrict__ b2) {
    GEMM_BODY(Hc,
              g_s1 + (size_t)(blockIdx.y * 128 + (threadIdx.x >> 1)) * Hc + ((threadIdx.x & 1) * 4),
              W2   + (size_t)(blockIdx.x * 128 + (threadIdx.x >> 1)) * Hc + ((threadIdx.x & 1) * 4),
              b2, g_h2, Dc)
}

// ---------------------------------------------------------------------------
// Exact pairwise f32->f64 sums (order-noise ~1e-16, irrelevant to f32 result).
// ---------------------------------------------------------------------------
__device__ __forceinline__ double pair4(const float4& y) {
    return ((double)y.x + (double)y.y) + ((double)y.z + (double)y.w);
}
__device__ __forceinline__ double pair4sq(const float4& y, float mu) {
    const float dx = __fsub_rn(y.x, mu), dy = __fsub_rn(y.y, mu);
    const float dz = __fsub_rn(y.z, mu), dw = __fsub_rn(y.w, mu);
    return ((double)__fmul_rn(dx, dx) + (double)__fmul_rn(dy, dy)) +
           ((double)__fmul_rn(dz, dz) + (double)__fmul_rn(dw, dw));
}

// ---------------------------------------------------------------------------
// Row statistics (R5 structure, pairwise-tree f64 accumulation instead of a
// 48-deep serial DADD chain): one warp per row, row in registers, butterfly
// reduce. Arithmetic contract unchanged:
//   mu  = f32( f64sum(y) / N )
//   var = f32( f64sum( f32((y-mu)^2) ) / N )
//   rstd = 1.0f / sqrtf(var + 1e-5f)
// ---------------------------------------------------------------------------
template <int NC>
__global__ __launch_bounds__(256) void stats_kernel(
    const float* __restrict__ src, float* __restrict__ muA,
    float* __restrict__ rsA) {
    const int row = blockIdx.x * 8 + (threadIdx.x >> 5);
    const int lane = threadIdx.x & 31;
    const float* p = src + (size_t)row * NC;
    constexpr int J = NC / 128;
    float4 y[J];
    double ps[J];
#pragma unroll
    for (int j = 0; j < J; j++) {
        y[j] = *(const float4*)(p + lane * 4 + j * 128);
        ps[j] = pair4(y[j]);
    }
    // balanced tree over J partials
#pragma unroll
    for (int w = 1; w < J; w <<= 1) {
#pragma unroll
        for (int j = 0; j + w < J; j += 2 * w) ps[j] += ps[j + w];
    }
    double s = ps[0];
#pragma unroll
    for (int o = 16; o; o >>= 1) s += __shfl_xor_sync(0xffffffffu, s, o);
    const float mu = (float)(s / (double)NC);

#pragma unroll
    for (int j = 0; j < J; j++) ps[j] = pair4sq(y[j], mu);
#pragma unroll
    for (int w = 1; w < J; w <<= 1) {
#pragma unroll
        for (int j = 0; j + w < J; j += 2 * w) ps[j] += ps[j + w];
    }
    double s2 = ps[0];
#pragma unroll
    for (int o = 16; o; o >>= 1) s2 += __shfl_xor_sync(0xffffffffu, s2, o);
    const float var = (float)(s2 / (double)NC);
    if (lane == 0) {
        muA[row] = mu;
        rsA[row] = __fdiv_rn(1.0f, __fsqrt_rn(__fadd_rn(var, 1e-5f)));
    }
}

// Elementwise LIF step, bit-exact op sequence (no contraction):
#define LIF_STEP(Y, G, B, V, S)                                                \
    {                                                                          \
        const float yy = __fadd_rn(                                            \
            __fmul_rn(__fmul_rn(__fsub_rn((Y), mu), rs), (G)), (B));           \
        (V) = __fadd_rn((V), __fmul_rn(__fsub_rn(yy, (V)), 0.5f));             \
        (S) = ((V) >= 1.0f) ? 1.f : 0.f;                                       \
        (V) = __fmul_rn((V), __fsub_rn(1.0f, (S)));                            \
    }

// ---------------------------------------------------------------------------
// LIF layer 1: pure streaming. One block per (b,l); 384 threads x float4
// cover H=1536. Membrane v in registers across T.  (R5-identical)
// ---------------------------------------------------------------------------
__global__ __launch_bounds__(384) void lif1_kernel(
    const float* __restrict__ g1, const float* __restrict__ be1) {
    const int bl = blockIdx.x;
    const int bI = bl / Lc, l = bl % Lc;
    const int c = threadIdx.x * 4;
    const float4 gg = *(const float4*)(g1 + c);
    const float4 bb = *(const float4*)(be1 + c);
    float4 v = {0.f, 0.f, 0.f, 0.f};
    const int rbase = bI * Lc + l;
#pragma unroll
    for (int t = 0; t < Tc; t++) {
        const int r = t * (Bc * Lc) + rbase;
        const size_t off = (size_t)r * Hc + c;
        const float4 y = *(const float4*)(g_h1 + off);
        const float mu = g_mu1[r], rs = g_rs1[r];
        float4 sp;
        LIF_STEP(y.x, gg.x, bb.x, v.x, sp.x)
        LIF_STEP(y.y, gg.y, bb.y, v.y, sp.y)
        LIF_STEP(y.z, gg.z, bb.z, v.z, sp.z)
        LIF_STEP(y.w, gg.w, bb.w, v.w, sp.w)
        *(float4*)(g_s1 + off) = sp;
    }
}

// ---------------------------------------------------------------------------
// LIF layer 2 -> final output [B,T,L,D]. 384 threads = 4 rows x 96 lanes x
// float4 (D=384).  (R5-identical)
// ---------------------------------------------------------------------------
__global__ __launch_bounds__(384) void lif2_kernel(
    const float* __restrict__ g2, const float* __restrict__ be2,
    float* __restrict__ out) {
    const int sub = threadIdx.x / 96;        // 0..3
    const int bl = blockIdx.x * 4 + sub;
    const int bI = bl / Lc, l = bl % Lc;
    const int c = (threadIdx.x % 96) * 4;
    const float4 gg = *(const float4*)(g2 + c);
    const float4 bb = *(const float4*)(be2 + c);
    float4 v = {0.f, 0.f, 0.f, 0.f};
    const int rbase = bI * Lc + l;
#pragma unroll
    for (int t = 0; t < Tc; t++) {
        const int r = t * (Bc * Lc) + rbase;
        const size_t off = (size_t)r * Dc + c;
        const float4 y = *(const float4*)(g_h2 + off);
        const float mu = g_mu2[r], rs = g_rs2[r];
        float4 sp;
        LIF_STEP(y.x, gg.x, bb.x, v.x, sp.x)
        LIF_STEP(y.y, gg.y, bb.y, v.y, sp.y)
        LIF_STEP(y.z, gg.z, bb.z, v.z, sp.z)
        LIF_STEP(y.w, gg.w, bb.w, v.w, sp.w)
        const size_t oo = (size_t)((bI * Tc + t) * Lc + l) * Dc + c;
        *(float4*)(out + oo) = sp;
    }
}

// ---------------------------------------------------------------------------
extern "C" void kernel_launch(void* const* d_in, const int* in_sizes, int n_in,
                              void* d_out, int out_size) {
    const float* x   = (const float*)d_in[0];
    const float* W1  = (const float*)d_in[1];
    const float* b1  = (const float*)d_in[2];
    const float* g1  = (const float*)d_in[3];
    const float* be1 = (const float*)d_in[4];
    const float* W2  = (const float*)d_in[5];
    const float* b2  = (const float*)d_in[6];
    const float* g2  = (const float*)d_in[7];
    const float* be2 = (const float*)d_in[8];
    float* out = (float*)d_out;

    float *mu1, *rs1, *mu2, *rs2, *h1, *h2;
    cudaGetSymbolAddress((void**)&mu1, g_mu1);
    cudaGetSymbolAddress((void**)&rs1, g_rs1);
    cudaGetSymbolAddress((void**)&mu2, g_mu2);
    cudaGetSymbolAddress((void**)&rs2, g_rs2);
    cudaGetSymbolAddress((void**)&h1, g_h1);
    cudaGetSymbolAddress((void**)&h2, g_h2);

    gemm1_kernel<<<dim3(Hc / 128, Mrows / 128), 256>>>(x, W1, b1);
    stats_kernel<Hc><<<Mrows / 8, 256>>>(h1, mu1, rs1);
    lif1_kernel<<<Bc * Lc, 384>>>(g1, be1);
    gemm2_kernel<<<dim3(Dc / 128, Mrows / 128), 256>>>(W2, b2);
    stats_kernel<Dc><<<Mrows / 8, 256>>>(h2, mu2, rs2);
    lif2_kernel<<<(Bc * Lc) / 4, 384>>>(g2, be2, out);
}

// round 10
// speedup vs baseline: 1.5211x; 1.3145x over previous
#include <cuda_runtime.h>
#include <cuda_bf16.h>
#include <math.h>

// Problem dims (fixed by reference setup_inputs)
constexpr int Bc = 32;
constexpr int Tc = 4;
constexpr int Lc = 196;
constexpr int Dc = 384;
constexpr int Hc = 1536;
constexpr int Mrows = Tc * Bc * Lc;   // 25088
constexpr int NB1 = Hc / 128;         // 12 n-blocks in gemm1
constexpr int NB2 = Dc / 128;         // 3 n-blocks in gemm2

// Scratch (device globals; allocation-free per harness rules)
__device__ float g_h1[(size_t)Mrows * Hc];   // pre-LN GEMM1 output  (~154 MB)
__device__ float g_s1[(size_t)Mrows * Hc];   // spikes layer 1       (~154 MB)
__device__ float g_h2[(size_t)Mrows * Dc];   // pre-LN GEMM2 output  (~38 MB)
__device__ float2 g_p1[(size_t)Mrows * NB1]; // (sum, sumsq) partials layer 1
__device__ float2 g_p2[(size_t)Mrows * NB2]; // (sum, sumsq) partials layer 2

// ---------------------------------------------------------------------------
// GEMM core (R9 mainloop, proven): 128x128 tile, BK=8, 256 threads, 8x8 per
// thread (split 4+4, conflict-free), double-buffered, 1 sync/iter.
// Bit-exactness contract: each output element is ONE fp32 FMA chain with k
// strictly ascending 0..K-1, bias added as a single separate __fadd_rn.
// NEW: epilogue additionally emits per-row partial (sum, sumsq) over this
// CTA's 128 columns (fixed f32 pairwise trees -> deterministic).
// ---------------------------------------------------------------------------
#define P4(a, b, c, d) (((a) + (b)) + ((c) + (d)))

#define GEMM_BODY(K_DIM, APTR_EXPR, BPTR_EXPR, BIAS, OUTBASE, OUT_LD, PART, NB)\
    constexpr int BK = 8;                                                      \
    constexpr int LDS_ = 132;                                                  \
    __shared__ float As[2][BK][LDS_];                                          \
    __shared__ float Bs[2][BK][LDS_];                                          \
    __shared__ float sp[16][132];                                              \
    __shared__ float sq[16][132];                                              \
    const int tid = threadIdx.x;                                               \
    const int lr = tid >> 1;                                                   \
    const int lc = (tid & 1) * 4;                                              \
    const float* aptr = (APTR_EXPR);                                           \
    const float* bptr = (BPTR_EXPR);                                           \
    const int tx = tid & 15;                                                   \
    const int ty = tid >> 4;                                                   \
    float acc[8][8] = {};                                                      \
    float4 av = *(const float4*)aptr;                                          \
    float4 bv = *(const float4*)bptr;                                          \
    int buf = 0;                                                               \
    As[0][lc + 0][lr] = av.x; As[0][lc + 1][lr] = av.y;                        \
    As[0][lc + 2][lr] = av.z; As[0][lc + 3][lr] = av.w;                        \
    Bs[0][lc + 0][lr] = bv.x; Bs[0][lc + 1][lr] = bv.y;                        \
    Bs[0][lc + 2][lr] = bv.z; Bs[0][lc + 3][lr] = bv.w;                        \
    __syncthreads();                                                           \
    for (int k0 = BK; k0 < (K_DIM) + BK; k0 += BK) {                           \
        const bool more = (k0 < (K_DIM));                                      \
        if (more) {                                                            \
            av = *(const float4*)(aptr + k0);                                  \
            bv = *(const float4*)(bptr + k0);                                  \
        }                                                                      \
        _Pragma("unroll")                                                      \
        for (int k = 0; k < BK; k++) {                                         \
            const float4 a0 = *(const float4*)&As[buf][k][ty * 4];             \
            const float4 a1 = *(const float4*)&As[buf][k][64 + ty * 4];        \
            const float4 b0 = *(const float4*)&Bs[buf][k][tx * 4];             \
            const float4 b1 = *(const float4*)&Bs[buf][k][64 + tx * 4];        \
            const float am[8] = {a0.x, a0.y, a0.z, a0.w, a1.x, a1.y, a1.z, a1.w}; \
            const float bn[8] = {b0.x, b0.y, b0.z, b0.w, b1.x, b1.y, b1.z, b1.w}; \
            _Pragma("unroll")                                                  \
            for (int i = 0; i < 8; i++) {                                      \
                _Pragma("unroll")                                              \
                for (int j = 0; j < 8; j++)                                    \
                    acc[i][j] = __fmaf_rn(am[i], bn[j], acc[i][j]);            \
            }                                                                  \
        }                                                                      \
        if (more) {                                                            \
            buf ^= 1;                                                          \
            As[buf][lc + 0][lr] = av.x; As[buf][lc + 1][lr] = av.y;            \
            As[buf][lc + 2][lr] = av.z; As[buf][lc + 3][lr] = av.w;            \
            Bs[buf][lc + 0][lr] = bv.x; Bs[buf][lc + 1][lr] = bv.y;            \
            Bs[buf][lc + 2][lr] = bv.z; Bs[buf][lc + 3][lr] = bv.w;            \
            __syncthreads();                                                   \
        }                                                                      \
    }                                                                          \
    const int n_base = blockIdx.x * 128;                                       \
    const int m_base = blockIdx.y * 128;                                       \
    const float4 bb0 = *(const float4*)((BIAS) + n_base + tx * 4);             \
    const float4 bb1 = *(const float4*)((BIAS) + n_base + 64 + tx * 4);        \
    _Pragma("unroll")                                                          \
    for (int i = 0; i < 8; i++) {                                              \
        const int ml = (i < 4) ? (ty * 4 + i) : (64 + ty * 4 + i - 4);         \
        float* o = (OUTBASE) + (size_t)(m_base + ml) * (OUT_LD) + n_base;      \
        float4 o0, o1;                                                         \
        o0.x = __fadd_rn(acc[i][0], bb0.x); o0.y = __fadd_rn(acc[i][1], bb0.y);\
        o0.z = __fadd_rn(acc[i][2], bb0.z); o0.w = __fadd_rn(acc[i][3], bb0.w);\
        o1.x = __fadd_rn(acc[i][4], bb1.x); o1.y = __fadd_rn(acc[i][5], bb1.y);\
        o1.z = __fadd_rn(acc[i][6], bb1.z); o1.w = __fadd_rn(acc[i][7], bb1.w);\
        *(float4*)(o + tx * 4) = o0;                                           \
        *(float4*)(o + 64 + tx * 4) = o1;                                      \
        sp[tx][ml] = P4(o0.x, o0.y, o0.z, o0.w) + P4(o1.x, o1.y, o1.z, o1.w);  \
        sq[tx][ml] = P4(o0.x * o0.x, o0.y * o0.y, o0.z * o0.z, o0.w * o0.w) +  \
                     P4(o1.x * o1.x, o1.y * o1.y, o1.z * o1.z, o1.w * o1.w);   \
    }                                                                          \
    __syncthreads();                                                           \
    if (tid < 128) {                                                           \
        float a = P4(P4(sp[0][tid], sp[1][tid], sp[2][tid], sp[3][tid]),       \
                     P4(sp[4][tid], sp[5][tid], sp[6][tid], sp[7][tid]),       \
                     P4(sp[8][tid], sp[9][tid], sp[10][tid], sp[11][tid]),     \
                     P4(sp[12][tid], sp[13][tid], sp[14][tid], sp[15][tid]));  \
        float b = P4(P4(sq[0][tid], sq[1][tid], sq[2][tid], sq[3][tid]),       \
                     P4(sq[4][tid], sq[5][tid], sq[6][tid], sq[7][tid]),       \
                     P4(sq[8][tid], sq[9][tid], sq[10][tid], sq[11][tid]),     \
                     P4(sq[12][tid], sq[13][tid], sq[14][tid], sq[15][tid]));  \
        (PART)[(size_t)(m_base + tid) * (NB) + blockIdx.x] = make_float2(a, b);\
    }

__global__ __launch_bounds__(256) void gemm1_kernel(
    const float* __restrict__ x, const float* __restrict__ W1,
    const float* __restrict__ b1) {
    // A row r = (t*B + b)*L + l maps into x at ((b*T + t)*L + l)*D
    const int r_ = blockIdx.y * 128 + (threadIdx.x >> 1);
    const int l_  = r_ % Lc;
    const int tb_ = r_ / Lc;
    const int bI_ = tb_ % Bc;
    const int tI_ = tb_ / Bc;
    GEMM_BODY(Dc,
              x  + (size_t)((bI_ * Tc + tI_) * Lc + l_) * Dc + ((threadIdx.x & 1) * 4),
              W1 + (size_t)(blockIdx.x * 128 + (threadIdx.x >> 1)) * Dc + ((threadIdx.x & 1) * 4),
              b1, g_h1, Hc, g_p1, NB1)
}

__global__ __launch_bounds__(256) void gemm2_kernel(
    const float* __restrict__ W2, const float* __restrict__ b2) {
    GEMM_BODY(Hc,
              g_s1 + (size_t)(blockIdx.y * 128 + (threadIdx.x >> 1)) * Hc + ((threadIdx.x & 1) * 4),
              W2   + (size_t)(blockIdx.x * 128 + (threadIdx.x >> 1)) * Hc + ((threadIdx.x & 1) * 4),
              b2, g_h2, Dc, g_p2, NB2)
}

// ---------------------------------------------------------------------------
// Combine partials -> (mu, rstd). f64 pairwise; var = E[y^2] - mu^2.
// Perturbation vs the reference's two-pass f32 var is ~1e-7 relative -- inside
// the demonstrated flip-free slack.
// ---------------------------------------------------------------------------
__device__ __forceinline__ float2 stats_from_p1(const float2* p) {
    double s[NB1], q[NB1];
#pragma unroll
    for (int j = 0; j < NB1; j++) { float2 v = p[j]; s[j] = v.x; q[j] = v.y; }
    const double S = (((s[0] + s[1]) + (s[2] + s[3])) +
                      ((s[4] + s[5]) + (s[6] + s[7]))) +
                     ((s[8] + s[9]) + (s[10] + s[11]));
    const double Q = (((q[0] + q[1]) + (q[2] + q[3])) +
                      ((q[4] + q[5]) + (q[6] + q[7]))) +
                     ((q[8] + q[9]) + (q[10] + q[11]));
    const double mu_d = S / (double)Hc;
    const float mu = (float)mu_d;
    const float var = (float)(Q / (double)Hc - mu_d * mu_d);
    return make_float2(mu, __fdiv_rn(1.0f, __fsqrt_rn(__fadd_rn(var, 1e-5f))));
}
__device__ __forceinline__ float2 stats_from_p2(const float2* p) {
    const float2 a = p[0], b = p[1], c = p[2];
    const double S = ((double)a.x + (double)b.x) + (double)c.x;
    const double Q = ((double)a.y + (double)b.y) + (double)c.y;
    const double mu_d = S / (double)Dc;
    const float mu = (float)mu_d;
    const float var = (float)(Q / (double)Dc - mu_d * mu_d);
    return make_float2(mu, __fdiv_rn(1.0f, __fsqrt_rn(__fadd_rn(var, 1e-5f))));
}

// Elementwise LIF step, bit-exact op sequence (no contraction):
#define LIF_STEP(Y, G, B, V, S)                                                \
    {                                                                          \
        const float yy = __fadd_rn(                                            \
            __fmul_rn(__fmul_rn(__fsub_rn((Y), mu), rs), (G)), (B));           \
        (V) = __fadd_rn((V), __fmul_rn(__fsub_rn(yy, (V)), 0.5f));             \
        (S) = ((V) >= 1.0f) ? 1.f : 0.f;                                       \
        (V) = __fmul_rn((V), __fsub_rn(1.0f, (S)));                            \
    }

// ---------------------------------------------------------------------------
// LIF layer 1: one block per (b,l); 384 threads x float4 cover H=1536.
// Threads 0..3 compute (mu, rstd) for their timestep from the partials.
// ---------------------------------------------------------------------------
__global__ __launch_bounds__(384) void lif1_kernel(
    const float* __restrict__ g1, const float* __restrict__ be1) {
    __shared__ float2 st[Tc];
    const int bl = blockIdx.x;
    const int bI = bl / Lc, l = bl % Lc;
    const int rbase = bI * Lc + l;
    if (threadIdx.x < Tc) {
        const int r = threadIdx.x * (Bc * Lc) + rbase;
        st[threadIdx.x] = stats_from_p1(g_p1 + (size_t)r * NB1);
    }
    const int c = threadIdx.x * 4;
    const float4 gg = *(const float4*)(g1 + c);
    const float4 bb = *(const float4*)(be1 + c);
    float4 v = {0.f, 0.f, 0.f, 0.f};
    __syncthreads();
#pragma unroll
    for (int t = 0; t < Tc; t++) {
        const int r = t * (Bc * Lc) + rbase;
        const size_t off = (size_t)r * Hc + c;
        const float4 y = *(const float4*)(g_h1 + off);
        const float mu = st[t].x, rs = st[t].y;
        float4 sp;
        LIF_STEP(y.x, gg.x, bb.x, v.x, sp.x)
        LIF_STEP(y.y, gg.y, bb.y, v.y, sp.y)
        LIF_STEP(y.z, gg.z, bb.z, v.z, sp.z)
        LIF_STEP(y.w, gg.w, bb.w, v.w, sp.w)
        *(float4*)(g_s1 + off) = sp;
    }
}

// ---------------------------------------------------------------------------
// LIF layer 2 -> final output [B,T,L,D]. 384 threads = 4 (b,l) rows x 96
// lanes x float4 (D=384). Threads 0..15 compute stats for (sub, t).
// ---------------------------------------------------------------------------
__global__ __launch_bounds__(384) void lif2_kernel(
    const float* __restrict__ g2, const float* __restrict__ be2,
    float* __restrict__ out) {
    __shared__ float2 st[4][Tc];
    if (threadIdx.x < 16) {
        const int sub_ = threadIdx.x >> 2;
        const int t_ = threadIdx.x & 3;
        const int bl_ = blockIdx.x * 4 + sub_;
        const int r = t_ * (Bc * Lc) + (bl_ / Lc) * Lc + (bl_ % Lc);
        st[sub_][t_] = stats_from_p2(g_p2 + (size_t)r * NB2);
    }
    const int sub = threadIdx.x / 96;        // 0..3
    const int bl = blockIdx.x * 4 + sub;
    const int bI = bl / Lc, l = bl % Lc;
    const int c = (threadIdx.x % 96) * 4;
    const float4 gg = *(const float4*)(g2 + c);
    const float4 bb = *(const float4*)(be2 + c);
    float4 v = {0.f, 0.f, 0.f, 0.f};
    const int rbase = bI * Lc + l;
    __syncthreads();
#pragma unroll
    for (int t = 0; t < Tc; t++) {
        const int r = t * (Bc * Lc) + rbase;
        const size_t off = (size_t)r * Dc + c;
        const float4 y = *(const float4*)(g_h2 + off);
        const float mu = st[sub][t].x, rs = st[sub][t].y;
        float4 sp;
        LIF_STEP(y.x, gg.x, bb.x, v.x, sp.x)
        LIF_STEP(y.y, gg.y, bb.y, v.y, sp.y)
        LIF_STEP(y.z, gg.z, bb.z, v.z, sp.z)
        LIF_STEP(y.w, gg.w, bb.w, v.w, sp.w)
        const size_t oo = (size_t)((bI * Tc + t) * Lc + l) * Dc + c;
        *(float4*)(out + oo) = sp;
    }
}

// ---------------------------------------------------------------------------
extern "C" void kernel_launch(void* const* d_in, const int* in_sizes, int n_in,
                              void* d_out, int out_size) {
    const float* x   = (const float*)d_in[0];
    const float* W1  = (const float*)d_in[1];
    const float* b1  = (const float*)d_in[2];
    const float* g1  = (const float*)d_in[3];
    const float* be1 = (const float*)d_in[4];
    const float* W2  = (const float*)d_in[5];
    const float* b2  = (const float*)d_in[6];
    const float* g2  = (const float*)d_in[7];
    const float* be2 = (const float*)d_in[8];
    float* out = (float*)d_out;

    gemm1_kernel<<<dim3(Hc / 128, Mrows / 128), 256>>>(x, W1, b1);
    lif1_kernel<<<Bc * Lc, 384>>>(g1, be1);
    gemm2_kernel<<<dim3(Dc / 128, Mrows / 128), 256>>>(W2, b2);
    lif2_kernel<<<(Bc * Lc) / 4, 384>>>(g2, be2, out);
}

// round 11
// speedup vs baseline: 2.1848x; 1.4363x over previous
#include <cuda_runtime.h>
#include <cuda_bf16.h>
#include <cuda_pipeline.h>
#include <math.h>

// Problem dims (fixed by reference setup_inputs)
constexpr int Bc = 32;
constexpr int Tc = 4;
constexpr int Lc = 196;
constexpr int Dc = 384;
constexpr int Hc = 1536;
constexpr int Mrows = Tc * Bc * Lc;   // 25088
constexpr int NB1 = Hc / 128;         // 12 n-blocks in gemm1

// Sparse gemm2 config
constexpr int CHUNK = 64;                 // k per smem chunk
constexpr int NCHUNK = Hc / CHUNK;        // 24
constexpr int CHUNK_FLOATS = CHUNK * Dc;  // 24576 floats = 96KB
constexpr int SP_THREADS = 1024;          // 32 warps
constexpr int SP_ROWS = 64;               // 2 rows per warp

// Scratch (device globals; allocation-free per harness rules)
__device__ float g_h1[(size_t)Mrows * Hc];   // pre-LN GEMM1 output  (~154 MB)
__device__ float g_s1[(size_t)Mrows * Hc];   // spikes layer 1       (~154 MB)
__device__ float g_h2[(size_t)Mrows * Dc];   // pre-LN GEMM2 output  (~38 MB)
__device__ float2 g_p1[(size_t)Mrows * NB1]; // (sum, sumsq) partials layer 1
__device__ float g_w2t[(size_t)Hc * Dc];     // W2 transposed [k][d] (2.4 MB)
__device__ float2 g_st2[Mrows];              // (mu, rstd) per layer-2 row

// ---------------------------------------------------------------------------
// GEMM1 (R10, proven): 128x128 tile, BK=8, 256 threads, 8x8/thread (4+4 split,
// conflict-free), double-buffered, epilogue emits per-row (sum,sumsq) partials.
// Bit-exact: each output is ONE fp32 FMA chain ascending k; bias separate.
// ---------------------------------------------------------------------------
#define P4(a, b, c, d) (((a) + (b)) + ((c) + (d)))

__global__ __launch_bounds__(256) void gemm1_kernel(
    const float* __restrict__ x, const float* __restrict__ W1,
    const float* __restrict__ b1) {
    constexpr int BK = 8;
    constexpr int LDS_ = 132;
    __shared__ float As[2][BK][LDS_];
    __shared__ float Bs[2][BK][LDS_];
    __shared__ float sp[16][132];
    __shared__ float sq[16][132];
    const int tid = threadIdx.x;
    const int lr = tid >> 1;
    const int lc = (tid & 1) * 4;

    // A row r = (t*B + b)*L + l maps into x at ((b*T + t)*L + l)*D
    const int r_ = blockIdx.y * 128 + lr;
    const int l_  = r_ % Lc;
    const int tb_ = r_ / Lc;
    const int bI_ = tb_ % Bc;
    const int tI_ = tb_ / Bc;
    const float* aptr = x + (size_t)((bI_ * Tc + tI_) * Lc + l_) * Dc + lc;
    const float* bptr = W1 + (size_t)(blockIdx.x * 128 + lr) * Dc + lc;

    const int tx = tid & 15;
    const int ty = tid >> 4;
    float acc[8][8] = {};
    float4 av = *(const float4*)aptr;
    float4 bv = *(const float4*)bptr;
    int buf = 0;
    As[0][lc + 0][lr] = av.x; As[0][lc + 1][lr] = av.y;
    As[0][lc + 2][lr] = av.z; As[0][lc + 3][lr] = av.w;
    Bs[0][lc + 0][lr] = bv.x; Bs[0][lc + 1][lr] = bv.y;
    Bs[0][lc + 2][lr] = bv.z; Bs[0][lc + 3][lr] = bv.w;
    __syncthreads();
    for (int k0 = BK; k0 < Dc + BK; k0 += BK) {
        const bool more = (k0 < Dc);
        if (more) {
            av = *(const float4*)(aptr + k0);
            bv = *(const float4*)(bptr + k0);
        }
#pragma unroll
        for (int k = 0; k < BK; k++) {
            const float4 a0 = *(const float4*)&As[buf][k][ty * 4];
            const float4 a1 = *(const float4*)&As[buf][k][64 + ty * 4];
            const float4 b0 = *(const float4*)&Bs[buf][k][tx * 4];
            const float4 b1 = *(const float4*)&Bs[buf][k][64 + tx * 4];
            const float am[8] = {a0.x, a0.y, a0.z, a0.w, a1.x, a1.y, a1.z, a1.w};
            const float bn[8] = {b0.x, b0.y, b0.z, b0.w, b1.x, b1.y, b1.z, b1.w};
#pragma unroll
            for (int i = 0; i < 8; i++) {
#pragma unroll
                for (int j = 0; j < 8; j++)
                    acc[i][j] = __fmaf_rn(am[i], bn[j], acc[i][j]);
            }
        }
        if (more) {
            buf ^= 1;
            As[buf][lc + 0][lr] = av.x; As[buf][lc + 1][lr] = av.y;
            As[buf][lc + 2][lr] = av.z; As[buf][lc + 3][lr] = av.w;
            Bs[buf][lc + 0][lr] = bv.x; Bs[buf][lc + 1][lr] = bv.y;
            Bs[buf][lc + 2][lr] = bv.z; Bs[buf][lc + 3][lr] = bv.w;
            __syncthreads();
        }
    }
    const int n_base = blockIdx.x * 128;
    const int m_base = blockIdx.y * 128;
    const float4 bb0 = *(const float4*)(b1 + n_base + tx * 4);
    const float4 bb1 = *(const float4*)(b1 + n_base + 64 + tx * 4);
#pragma unroll
    for (int i = 0; i < 8; i++) {
        const int ml = (i < 4) ? (ty * 4 + i) : (64 + ty * 4 + i - 4);
        float* o = g_h1 + (size_t)(m_base + ml) * Hc + n_base;
        float4 o0, o1;
        o0.x = __fadd_rn(acc[i][0], bb0.x); o0.y = __fadd_rn(acc[i][1], bb0.y);
        o0.z = __fadd_rn(acc[i][2], bb0.z); o0.w = __fadd_rn(acc[i][3], bb0.w);
        o1.x = __fadd_rn(acc[i][4], bb1.x); o1.y = __fadd_rn(acc[i][5], bb1.y);
        o1.z = __fadd_rn(acc[i][6], bb1.z); o1.w = __fadd_rn(acc[i][7], bb1.w);
        *(float4*)(o + tx * 4) = o0;
        *(float4*)(o + 64 + tx * 4) = o1;
        sp[tx][ml] = P4(o0.x, o0.y, o0.z, o0.w) + P4(o1.x, o1.y, o1.z, o1.w);
        sq[tx][ml] = P4(o0.x * o0.x, o0.y * o0.y, o0.z * o0.z, o0.w * o0.w) +
                     P4(o1.x * o1.x, o1.y * o1.y, o1.z * o1.z, o1.w * o1.w);
    }
    __syncthreads();
    if (tid < 128) {
        float a = P4(P4(sp[0][tid], sp[1][tid], sp[2][tid], sp[3][tid]),
                     P4(sp[4][tid], sp[5][tid], sp[6][tid], sp[7][tid]),
                     P4(sp[8][tid], sp[9][tid], sp[10][tid], sp[11][tid]),
                     P4(sp[12][tid], sp[13][tid], sp[14][tid], sp[15][tid]));
        float b = P4(P4(sq[0][tid], sq[1][tid], sq[2][tid], sq[3][tid]),
                     P4(sq[4][tid], sq[5][tid], sq[6][tid], sq[7][tid]),
                     P4(sq[8][tid], sq[9][tid], sq[10][tid], sq[11][tid]),
                     P4(sq[12][tid], sq[13][tid], sq[14][tid], sq[15][tid]));
        g_p1[(size_t)(m_base + tid) * NB1 + blockIdx.x] = make_float2(a, b);
    }
}

// ---------------------------------------------------------------------------
// W2 transpose: W2 [D][H] -> g_w2t [H][D].
// ---------------------------------------------------------------------------
__global__ void w2t_kernel(const float* __restrict__ W2) {
    __shared__ float tile[32][33];
    const int kb = blockIdx.x * 32, db = blockIdx.y * 32;
    const int tx = threadIdx.x, ty = threadIdx.y;
    for (int i = ty; i < 32; i += 8)
        tile[i][tx] = W2[(size_t)(db + i) * Hc + kb + tx];
    __syncthreads();
    for (int i = ty; i < 32; i += 8)
        g_w2t[(size_t)(kb + i) * Dc + db + tx] = tile[tx][i];
}

// ---------------------------------------------------------------------------
// Combine gemm1 partials -> (mu, rstd). f64 pairwise; var = E[y^2] - mu^2.
// ---------------------------------------------------------------------------
__device__ __forceinline__ float2 stats_from_p1(const float2* p) {
    double s[NB1], q[NB1];
#pragma unroll
    for (int j = 0; j < NB1; j++) { float2 v = p[j]; s[j] = v.x; q[j] = v.y; }
    const double S = (((s[0] + s[1]) + (s[2] + s[3])) +
                      ((s[4] + s[5]) + (s[6] + s[7]))) +
                     ((s[8] + s[9]) + (s[10] + s[11]));
    const double Q = (((q[0] + q[1]) + (q[2] + q[3])) +
                      ((q[4] + q[5]) + (q[6] + q[7]))) +
                     ((q[8] + q[9]) + (q[10] + q[11]));
    const double mu_d = S / (double)Hc;
    const float mu = (float)mu_d;
    const float var = (float)(Q / (double)Hc - mu_d * mu_d);
    return make_float2(mu, __fdiv_rn(1.0f, __fsqrt_rn(__fadd_rn(var, 1e-5f))));
}

// Elementwise LIF step, bit-exact op sequence (no contraction):
#define LIF_STEP(Y, G, B, V, S)                                                \
    {                                                                          \
        const float yy = __fadd_rn(                                            \
            __fmul_rn(__fmul_rn(__fsub_rn((Y), mu), rs), (G)), (B));           \
        (V) = __fadd_rn((V), __fmul_rn(__fsub_rn(yy, (V)), 0.5f));             \
        (S) = ((V) >= 1.0f) ? 1.f : 0.f;                                       \
        (V) = __fmul_rn((V), __fsub_rn(1.0f, (S)));                            \
    }

// ---------------------------------------------------------------------------
// LIF layer 1 (R10): one block per (b,l); 384 threads x float4 cover H=1536.
// ---------------------------------------------------------------------------
__global__ __launch_bounds__(384) void lif1_kernel(
    const float* __restrict__ g1, const float* __restrict__ be1) {
    __shared__ float2 st[Tc];
    const int bl = blockIdx.x;
    const int bI = bl / Lc, l = bl % Lc;
    const int rbase = bI * Lc + l;
    if (threadIdx.x < Tc) {
        const int r = threadIdx.x * (Bc * Lc) + rbase;
        st[threadIdx.x] = stats_from_p1(g_p1 + (size_t)r * NB1);
    }
    const int c = threadIdx.x * 4;
    const float4 gg = *(const float4*)(g1 + c);
    const float4 bb = *(const float4*)(be1 + c);
    float4 v = {0.f, 0.f, 0.f, 0.f};
    __syncthreads();
#pragma unroll
    for (int t = 0; t < Tc; t++) {
        const int r = t * (Bc * Lc) + rbase;
        const size_t off = (size_t)r * Hc + c;
        const float4 y = *(const float4*)(g_h1 + off);
        const float mu = st[t].x, rs = st[t].y;
        float4 sp;
        LIF_STEP(y.x, gg.x, bb.x, v.x, sp.x)
        LIF_STEP(y.y, gg.y, bb.y, v.y, sp.y)
        LIF_STEP(y.z, gg.z, bb.z, v.z, sp.z)
        LIF_STEP(y.w, gg.w, bb.w, v.w, sp.w)
        *(float4*)(g_s1 + off) = sp;
    }
}

// ---------------------------------------------------------------------------
// Sparse-exact GEMM2: h2[m,d] = b2[d] + sum_{k: s1[m,k]=1} W2T[k,d], adds in
// ascending k. Bit-identical to the dense fp32 fma chain (fma(0,..)=acc,
// fma(1,w,acc)=fadd(w,acc); acc never -0).
// CTA = 64 rows, 1024 threads (32 warps x 2 rows). W2T k-chunks (64x384 =
// 96KB) double-buffered in smem via cp.async. Warp-uniform ffsll walk over
// the 2-row spike mask; select-multiplier FMA (no divergent branches).
// Epilogue: bias add + store + per-row (mu, rstd).
// ---------------------------------------------------------------------------
#define ACC_ROW(F, A0, A1, A2)                                                 \
    A0.x = __fmaf_rn(F, w0.x, A0.x); A0.y = __fmaf_rn(F, w0.y, A0.y);          \
    A0.z = __fmaf_rn(F, w0.z, A0.z); A0.w = __fmaf_rn(F, w0.w, A0.w);          \
    A1.x = __fmaf_rn(F, w1.x, A1.x); A1.y = __fmaf_rn(F, w1.y, A1.y);          \
    A1.z = __fmaf_rn(F, w1.z, A1.z); A1.w = __fmaf_rn(F, w1.w, A1.w);          \
    A2.x = __fmaf_rn(F, w2v.x, A2.x); A2.y = __fmaf_rn(F, w2v.y, A2.y);        \
    A2.z = __fmaf_rn(F, w2v.z, A2.z); A2.w = __fmaf_rn(F, w2v.w, A2.w);

__global__ __launch_bounds__(SP_THREADS) void spmm2_kernel(
    const float* __restrict__ b2) {
    extern __shared__ float w2s[];   // 2 * CHUNK_FLOATS
    const int tid = threadIdx.x;
    const int warp = tid >> 5, lane = tid & 31;
    const int rbase = blockIdx.x * SP_ROWS + warp * 2;
    const int lane12 = lane * 12;
    const unsigned FULL = 0xffffffffu;

    // prologue: async copy chunk 0
    {
        const float4* src = (const float4*)g_w2t;
        float4* dst = (float4*)w2s;
#pragma unroll
        for (int i = 0; i < 6; i++)
            __pipeline_memcpy_async(dst + tid + i * 1024, src + tid + i * 1024, 16);
        __pipeline_commit();
    }

    // s1 source: lanes 0-15 -> row0, 16-31 -> row1; each lane a float4 slice
    const int row_sel = rbase + (lane >> 4);
    const float* s1p = g_s1 + (size_t)row_sel * Hc + (lane & 15) * 4;
    float4 ycur = *(const float4*)s1p;

    float4 a00 = {0,0,0,0}, a01 = {0,0,0,0}, a02 = {0,0,0,0};
    float4 a10 = {0,0,0,0}, a11 = {0,0,0,0}, a12 = {0,0,0,0};

    for (int c = 0; c < NCHUNK; c++) {
        __syncthreads();   // all warps done reading buf[(c+1)&1] (chunk c-1)
        if (c + 1 < NCHUNK) {
            const float4* src = (const float4*)(g_w2t + (size_t)(c + 1) * CHUNK_FLOATS);
            float4* dst = (float4*)(w2s + ((c + 1) & 1) * CHUNK_FLOATS);
#pragma unroll
            for (int i = 0; i < 6; i++)
                __pipeline_memcpy_async(dst + tid + i * 1024, src + tid + i * 1024, 16);
            __pipeline_commit();
            __pipeline_wait_prior(1);
        } else {
            __pipeline_wait_prior(0);
        }
        __syncthreads();   // chunk c resident in buf[c&1]

        float4 ynext = make_float4(0.f, 0.f, 0.f, 0.f);
        if (c + 1 < NCHUNK) ynext = *(const float4*)(s1p + (c + 1) * CHUNK);

        // build 64-bit spike masks for the warp's 2 rows (k ascending by bit)
        unsigned mm = (ycur.x != 0.f ? 1u : 0u) | (ycur.y != 0.f ? 2u : 0u) |
                      (ycur.z != 0.f ? 4u : 0u) | (ycur.w != 0.f ? 8u : 0u);
        unsigned long long m = (unsigned long long)mm << ((lane & 15) * 4);
        m |= __shfl_xor_sync(FULL, m, 1);
        m |= __shfl_xor_sync(FULL, m, 2);
        m |= __shfl_xor_sync(FULL, m, 4);
        m |= __shfl_xor_sync(FULL, m, 8);
        const unsigned long long m0 = __shfl_sync(FULL, m, 0);
        const unsigned long long m1 = __shfl_sync(FULL, m, 16);

        const float* wbase = w2s + (c & 1) * CHUNK_FLOATS + lane12;
        unsigned long long u = m0 | m1;
        while (u) {
            const int j = __ffsll((long long)u) - 1;
            u &= u - 1;
            const float4* wr = (const float4*)(wbase + j * Dc);
            const float4 w0 = wr[0], w1 = wr[1], w2v = wr[2];
            const float f0 = (float)((unsigned)(m0 >> j) & 1u);
            const float f1 = (float)((unsigned)(m1 >> j) & 1u);
            ACC_ROW(f0, a00, a01, a02)
            ACC_ROW(f1, a10, a11, a12)
        }
        ycur = ynext;
    }

    // epilogue: bias, store h2, per-row stats
    const float4 bb0 = *(const float4*)(b2 + lane12);
    const float4 bb1 = *(const float4*)(b2 + lane12 + 4);
    const float4 bb2 = *(const float4*)(b2 + lane12 + 8);
#pragma unroll
    for (int rr = 0; rr < 2; rr++) {
        const float4 A0 = rr ? a10 : a00;
        const float4 A1 = rr ? a11 : a01;
        const float4 A2 = rr ? a12 : a02;
        float4 o0, o1, o2;
        o0.x = __fadd_rn(A0.x, bb0.x); o0.y = __fadd_rn(A0.y, bb0.y);
        o0.z = __fadd_rn(A0.z, bb0.z); o0.w = __fadd_rn(A0.w, bb0.w);
        o1.x = __fadd_rn(A1.x, bb1.x); o1.y = __fadd_rn(A1.y, bb1.y);
        o1.z = __fadd_rn(A1.z, bb1.z); o1.w = __fadd_rn(A1.w, bb1.w);
        o2.x = __fadd_rn(A2.x, bb2.x); o2.y = __fadd_rn(A2.y, bb2.y);
        o2.z = __fadd_rn(A2.z, bb2.z); o2.w = __fadd_rn(A2.w, bb2.w);
        const int row = rbase + rr;
        float* q = g_h2 + (size_t)row * Dc + lane12;
        *(float4*)q = o0; *(float4*)(q + 4) = o1; *(float4*)(q + 8) = o2;

        // f32 lane partials, f64 butterfly (same accuracy class as g_p1 path)
        const float sf = P4(o0.x, o0.y, o0.z, o0.w) +
                         P4(o1.x, o1.y, o1.z, o1.w) +
                         P4(o2.x, o2.y, o2.z, o2.w);
        const float qf = P4(o0.x * o0.x, o0.y * o0.y, o0.z * o0.z, o0.w * o0.w) +
                         P4(o1.x * o1.x, o1.y * o1.y, o1.z * o1.z, o1.w * o1.w) +
                         P4(o2.x * o2.x, o2.y * o2.y, o2.z * o2.z, o2.w * o2.w);
        double sd = (double)sf, qd = (double)qf;
#pragma unroll
        for (int o = 16; o; o >>= 1) {
            sd += __shfl_xor_sync(FULL, sd, o);
            qd += __shfl_xor_sync(FULL, qd, o);
        }
        if (lane == 0) {
            const double mu_d = sd / (double)Dc;
            const float var = (float)(qd / (double)Dc - mu_d * mu_d);
            g_st2[row] = make_float2(
                (float)mu_d,
                __fdiv_rn(1.0f, __fsqrt_rn(__fadd_rn(var, 1e-5f))));
        }
    }
}

// ---------------------------------------------------------------------------
// LIF layer 2 -> final output [B,T,L,D]. 384 threads = 4 (b,l) rows x 96
// lanes x float4 (D=384). Stats read from g_st2.
// ---------------------------------------------------------------------------
__global__ __launch_bounds__(384) void lif2_kernel(
    const float* __restrict__ g2, const float* __restrict__ be2,
    float* __restrict__ out) {
    __shared__ float2 st[4][Tc];
    if (threadIdx.x < 16) {
        const int sub_ = threadIdx.x >> 2;
        const int t_ = threadIdx.x & 3;
        const int bl_ = blockIdx.x * 4 + sub_;
        const int r = t_ * (Bc * Lc) + (bl_ / Lc) * Lc + (bl_ % Lc);
        st[sub_][t_] = g_st2[r];
    }
    const int sub = threadIdx.x / 96;        // 0..3
    const int bl = blockIdx.x * 4 + sub;
    const int bI = bl / Lc, l = bl % Lc;
    const int c = (threadIdx.x % 96) * 4;
    const float4 gg = *(const float4*)(g2 + c);
    const float4 bb = *(const float4*)(be2 + c);
    float4 v = {0.f, 0.f, 0.f, 0.f};
    const int rbase = bI * Lc + l;
    __syncthreads();
#pragma unroll
    for (int t = 0; t < Tc; t++) {
        const int r = t * (Bc * Lc) + rbase;
        const size_t off = (size_t)r * Dc + c;
        const float4 y = *(const float4*)(g_h2 + off);
        const float mu = st[sub][t].x, rs = st[sub][t].y;
        float4 sp;
        LIF_STEP(y.x, gg.x, bb.x, v.x, sp.x)
        LIF_STEP(y.y, gg.y, bb.y, v.y, sp.y)
        LIF_STEP(y.z, gg.z, bb.z, v.z, sp.z)
        LIF_STEP(y.w, gg.w, bb.w, v.w, sp.w)
        const size_t oo = (size_t)((bI * Tc + t) * Lc + l) * Dc + c;
        *(float4*)(out + oo) = sp;
    }
}

// ---------------------------------------------------------------------------
extern "C" void kernel_launch(void* const* d_in, const int* in_sizes, int n_in,
                              void* d_out, int out_size) {
    const float* x   = (const float*)d_in[0];
    const float* W1  = (const float*)d_in[1];
    const float* b1  = (const float*)d_in[2];
    const float* g1  = (const float*)d_in[3];
    const float* be1 = (const float*)d_in[4];
    const float* W2  = (const float*)d_in[5];
    const float* b2  = (const float*)d_in[6];
    const float* g2  = (const float*)d_in[7];
    const float* be2 = (const float*)d_in[8];
    float* out = (float*)d_out;

    cudaFuncSetAttribute(spmm2_kernel,
                         cudaFuncAttributeMaxDynamicSharedMemorySize,
                         2 * CHUNK_FLOATS * (int)sizeof(float));

    w2t_kernel<<<dim3(Hc / 32, Dc / 32), dim3(32, 8)>>>(W2);
    gemm1_kernel<<<dim3(Hc / 128, Mrows / 128), 256>>>(x, W1, b1);
    lif1_kernel<<<Bc * Lc, 384>>>(g1, be1);
    spmm2_kernel<<<Mrows / SP_ROWS, SP_THREADS,
                   2 * CHUNK_FLOATS * sizeof(float)>>>(b2);
    lif2_kernel<<<(Bc * Lc) / 4, 384>>>(g2, be2, out);
}

// round 12
// speedup vs baseline: 2.3044x; 1.0547x over previous
#include <cuda_runtime.h>
#include <cuda_bf16.h>
#include <cuda_pipeline.h>
#include <math.h>

// Problem dims (fixed by reference setup_inputs)
constexpr int Bc = 32;
constexpr int Tc = 4;
constexpr int Lc = 196;
constexpr int Dc = 384;
constexpr int Hc = 1536;
constexpr int Mrows = Tc * Bc * Lc;   // 25088
constexpr int NB1 = Hc / 128;         // 12 n-blocks in gemm1

// Sparse gemm2 config
constexpr int CHUNK = 64;                 // k per smem chunk
constexpr int NCHUNK = Hc / CHUNK;        // 24
constexpr int CHUNK_FLOATS = CHUNK * Dc;  // 24576 floats = 96KB
constexpr int SP_THREADS = 1024;          // 32 warps
constexpr int SP_ROWS = 64;               // 2 rows per warp

// Scratch (device globals; allocation-free per harness rules)
__device__ float g_h1[(size_t)Mrows * Hc];   // pre-LN GEMM1 output  (~154 MB)
__device__ float g_h2[(size_t)Mrows * Dc];   // pre-LN GEMM2 output  (~38 MB)
__device__ float2 g_p1[(size_t)Mrows * NB1]; // (sum, sumsq) partials layer 1
__device__ float g_w2t[(size_t)Hc * Dc];     // W2 transposed [k][d] (2.4 MB)
__device__ float2 g_st2[Mrows];              // (mu, rstd) per layer-2 row
__device__ unsigned long long g_m1[(size_t)Mrows * NCHUNK]; // spike bitmasks

// ---------------------------------------------------------------------------
// GEMM1 (R10, proven): 128x128 tile, BK=8, 256 threads, 8x8/thread (4+4 split,
// conflict-free), double-buffered, epilogue emits per-row (sum,sumsq) partials.
// Bit-exact: each output is ONE fp32 FMA chain ascending k; bias separate.
// ---------------------------------------------------------------------------
#define P4(a, b, c, d) (((a) + (b)) + ((c) + (d)))

__global__ __launch_bounds__(256) void gemm1_kernel(
    const float* __restrict__ x, const float* __restrict__ W1,
    const float* __restrict__ b1) {
    constexpr int BK = 8;
    constexpr int LDS_ = 132;
    __shared__ float As[2][BK][LDS_];
    __shared__ float Bs[2][BK][LDS_];
    __shared__ float sp[16][132];
    __shared__ float sq[16][132];
    const int tid = threadIdx.x;
    const int lr = tid >> 1;
    const int lc = (tid & 1) * 4;

    // A row r = (t*B + b)*L + l maps into x at ((b*T + t)*L + l)*D
    const int r_ = blockIdx.y * 128 + lr;
    const int l_  = r_ % Lc;
    const int tb_ = r_ / Lc;
    const int bI_ = tb_ % Bc;
    const int tI_ = tb_ / Bc;
    const float* aptr = x + (size_t)((bI_ * Tc + tI_) * Lc + l_) * Dc + lc;
    const float* bptr = W1 + (size_t)(blockIdx.x * 128 + lr) * Dc + lc;

    const int tx = tid & 15;
    const int ty = tid >> 4;
    float acc[8][8] = {};
    float4 av = *(const float4*)aptr;
    float4 bv = *(const float4*)bptr;
    int buf = 0;
    As[0][lc + 0][lr] = av.x; As[0][lc + 1][lr] = av.y;
    As[0][lc + 2][lr] = av.z; As[0][lc + 3][lr] = av.w;
    Bs[0][lc + 0][lr] = bv.x; Bs[0][lc + 1][lr] = bv.y;
    Bs[0][lc + 2][lr] = bv.z; Bs[0][lc + 3][lr] = bv.w;
    __syncthreads();
    for (int k0 = BK; k0 < Dc + BK; k0 += BK) {
        const bool more = (k0 < Dc);
        if (more) {
            av = *(const float4*)(aptr + k0);
            bv = *(const float4*)(bptr + k0);
        }
#pragma unroll
        for (int k = 0; k < BK; k++) {
            const float4 a0 = *(const float4*)&As[buf][k][ty * 4];
            const float4 a1 = *(const float4*)&As[buf][k][64 + ty * 4];
            const float4 b0 = *(const float4*)&Bs[buf][k][tx * 4];
            const float4 b1 = *(const float4*)&Bs[buf][k][64 + tx * 4];
            const float am[8] = {a0.x, a0.y, a0.z, a0.w, a1.x, a1.y, a1.z, a1.w};
            const float bn[8] = {b0.x, b0.y, b0.z, b0.w, b1.x, b1.y, b1.z, b1.w};
#pragma unroll
            for (int i = 0; i < 8; i++) {
#pragma unroll
                for (int j = 0; j < 8; j++)
                    acc[i][j] = __fmaf_rn(am[i], bn[j], acc[i][j]);
            }
        }
        if (more) {
            buf ^= 1;
            As[buf][lc + 0][lr] = av.x; As[buf][lc + 1][lr] = av.y;
            As[buf][lc + 2][lr] = av.z; As[buf][lc + 3][lr] = av.w;
            Bs[buf][lc + 0][lr] = bv.x; Bs[buf][lc + 1][lr] = bv.y;
            Bs[buf][lc + 2][lr] = bv.z; Bs[buf][lc + 3][lr] = bv.w;
            __syncthreads();
        }
    }
    const int n_base = blockIdx.x * 128;
    const int m_base = blockIdx.y * 128;
    const float4 bb0 = *(const float4*)(b1 + n_base + tx * 4);
    const float4 bb1 = *(const float4*)(b1 + n_base + 64 + tx * 4);
#pragma unroll
    for (int i = 0; i < 8; i++) {
        const int ml = (i < 4) ? (ty * 4 + i) : (64 + ty * 4 + i - 4);
        float* o = g_h1 + (size_t)(m_base + ml) * Hc + n_base;
        float4 o0, o1;
        o0.x = __fadd_rn(acc[i][0], bb0.x); o0.y = __fadd_rn(acc[i][1], bb0.y);
        o0.z = __fadd_rn(acc[i][2], bb0.z); o0.w = __fadd_rn(acc[i][3], bb0.w);
        o1.x = __fadd_rn(acc[i][4], bb1.x); o1.y = __fadd_rn(acc[i][5], bb1.y);
        o1.z = __fadd_rn(acc[i][6], bb1.z); o1.w = __fadd_rn(acc[i][7], bb1.w);
        *(float4*)(o + tx * 4) = o0;
        *(float4*)(o + 64 + tx * 4) = o1;
        sp[tx][ml] = P4(o0.x, o0.y, o0.z, o0.w) + P4(o1.x, o1.y, o1.z, o1.w);
        sq[tx][ml] = P4(o0.x * o0.x, o0.y * o0.y, o0.z * o0.z, o0.w * o0.w) +
                     P4(o1.x * o1.x, o1.y * o1.y, o1.z * o1.z, o1.w * o1.w);
    }
    __syncthreads();
    if (tid < 128) {
        float a = P4(P4(sp[0][tid], sp[1][tid], sp[2][tid], sp[3][tid]),
                     P4(sp[4][tid], sp[5][tid], sp[6][tid], sp[7][tid]),
                     P4(sp[8][tid], sp[9][tid], sp[10][tid], sp[11][tid]),
                     P4(sp[12][tid], sp[13][tid], sp[14][tid], sp[15][tid]));
        float b = P4(P4(sq[0][tid], sq[1][tid], sq[2][tid], sq[3][tid]),
                     P4(sq[4][tid], sq[5][tid], sq[6][tid], sq[7][tid]),
                     P4(sq[8][tid], sq[9][tid], sq[10][tid], sq[11][tid]),
                     P4(sq[12][tid], sq[13][tid], sq[14][tid], sq[15][tid]));
        g_p1[(size_t)(m_base + tid) * NB1 + blockIdx.x] = make_float2(a, b);
    }
}

// ---------------------------------------------------------------------------
// W2 transpose: W2 [D][H] -> g_w2t [H][D].
// ---------------------------------------------------------------------------
__global__ void w2t_kernel(const float* __restrict__ W2) {
    __shared__ float tile[32][33];
    const int kb = blockIdx.x * 32, db = blockIdx.y * 32;
    const int tx = threadIdx.x, ty = threadIdx.y;
    for (int i = ty; i < 32; i += 8)
        tile[i][tx] = W2[(size_t)(db + i) * Hc + kb + tx];
    __syncthreads();
    for (int i = ty; i < 32; i += 8)
        g_w2t[(size_t)(kb + i) * Dc + db + tx] = tile[tx][i];
}

// ---------------------------------------------------------------------------
// Combine gemm1 partials -> (mu, rstd). f64 pairwise; var = E[y^2] - mu^2.
// ---------------------------------------------------------------------------
__device__ __forceinline__ float2 stats_from_p1(const float2* p) {
    double s[NB1], q[NB1];
#pragma unroll
    for (int j = 0; j < NB1; j++) { float2 v = p[j]; s[j] = v.x; q[j] = v.y; }
    const double S = (((s[0] + s[1]) + (s[2] + s[3])) +
                      ((s[4] + s[5]) + (s[6] + s[7]))) +
                     ((s[8] + s[9]) + (s[10] + s[11]));
    const double Q = (((q[0] + q[1]) + (q[2] + q[3])) +
                      ((q[4] + q[5]) + (q[6] + q[7]))) +
                     ((q[8] + q[9]) + (q[10] + q[11]));
    const double mu_d = S / (double)Hc;
    const float mu = (float)mu_d;
    const float var = (float)(Q / (double)Hc - mu_d * mu_d);
    return make_float2(mu, __fdiv_rn(1.0f, __fsqrt_rn(__fadd_rn(var, 1e-5f))));
}

// Elementwise LIF step, bit-exact op sequence (no contraction):
#define LIF_STEP(Y, G, B, V, S)                                                \
    {                                                                          \
        const float yy = __fadd_rn(                                            \
            __fmul_rn(__fmul_rn(__fsub_rn((Y), mu), rs), (G)), (B));           \
        (V) = __fadd_rn((V), __fmul_rn(__fsub_rn(yy, (V)), 0.5f));             \
        (S) = ((V) >= 1.0f) ? 1.f : 0.f;                                       \
        (V) = __fmul_rn((V), __fsub_rn(1.0f, (S)));                            \
    }

// ---------------------------------------------------------------------------
// LIF layer 1: one block per (b,l); 384 threads x float4 cover H=1536.
// Emits PACKED BITMASKS (uint64 per 64 columns) instead of float spikes:
// bit (lane&15)*4+e of word 2*warp+(lane>>4) <-> column tid*4+e, k ascending.
// ---------------------------------------------------------------------------
__global__ __launch_bounds__(384) void lif1_kernel(
    const float* __restrict__ g1, const float* __restrict__ be1) {
    __shared__ float2 st[Tc];
    const int bl = blockIdx.x;
    const int bI = bl / Lc, l = bl % Lc;
    const int rbase = bI * Lc + l;
    if (threadIdx.x < Tc) {
        const int r = threadIdx.x * (Bc * Lc) + rbase;
        st[threadIdx.x] = stats_from_p1(g_p1 + (size_t)r * NB1);
    }
    const int c = threadIdx.x * 4;
    const int wp = threadIdx.x >> 5;
    const int lane = threadIdx.x & 31;
    const unsigned FULL = 0xffffffffu;
    const float4 gg = *(const float4*)(g1 + c);
    const float4 bb = *(const float4*)(be1 + c);
    float4 v = {0.f, 0.f, 0.f, 0.f};
    __syncthreads();
#pragma unroll
    for (int t = 0; t < Tc; t++) {
        const int r = t * (Bc * Lc) + rbase;
        const size_t off = (size_t)r * Hc + c;
        const float4 y = *(const float4*)(g_h1 + off);
        const float mu = st[t].x, rs = st[t].y;
        float4 sp;
        LIF_STEP(y.x, gg.x, bb.x, v.x, sp.x)
        LIF_STEP(y.y, gg.y, bb.y, v.y, sp.y)
        LIF_STEP(y.z, gg.z, bb.z, v.z, sp.z)
        LIF_STEP(y.w, gg.w, bb.w, v.w, sp.w)
        const unsigned mm = (sp.x != 0.f ? 1u : 0u) | (sp.y != 0.f ? 2u : 0u) |
                            (sp.z != 0.f ? 4u : 0u) | (sp.w != 0.f ? 8u : 0u);
        unsigned long long m = (unsigned long long)mm << ((lane & 15) * 4);
        m |= __shfl_xor_sync(FULL, m, 1);
        m |= __shfl_xor_sync(FULL, m, 2);
        m |= __shfl_xor_sync(FULL, m, 4);
        m |= __shfl_xor_sync(FULL, m, 8);
        if ((lane & 15) == 0)
            g_m1[(size_t)r * NCHUNK + 2 * wp + (lane >> 4)] = m;
    }
}

// ---------------------------------------------------------------------------
// Sparse-exact GEMM2: h2[m,d] = b2[d] + sum_{k: spike(m,k)} W2T[k,d], adds in
// ascending k. Bit-identical to the dense fp32 fma chain (fma(0,..)=acc,
// fma(1,w,acc)=fadd_rn(acc,w); acc never -0).
// CTA = 64 rows, 1024 threads (32 warps x 2 rows). W2T k-chunks (64x384 =
// 96KB) double-buffered in smem via cp.async. Per-row ffsll walks (FADD only
// for that row's spikes), interleaved across the warp's 2 rows for ILP.
// Epilogue: bias add + store + per-row (mu, rstd).
// ---------------------------------------------------------------------------
#define ADD_ROW(A0, A1, A2)                                                    \
    A0.x = __fadd_rn(A0.x, w0.x); A0.y = __fadd_rn(A0.y, w0.y);                \
    A0.z = __fadd_rn(A0.z, w0.z); A0.w = __fadd_rn(A0.w, w0.w);                \
    A1.x = __fadd_rn(A1.x, w1.x); A1.y = __fadd_rn(A1.y, w1.y);                \
    A1.z = __fadd_rn(A1.z, w1.z); A1.w = __fadd_rn(A1.w, w1.w);                \
    A2.x = __fadd_rn(A2.x, w2v.x); A2.y = __fadd_rn(A2.y, w2v.y);              \
    A2.z = __fadd_rn(A2.z, w2v.z); A2.w = __fadd_rn(A2.w, w2v.w);

__global__ __launch_bounds__(SP_THREADS) void spmm2_kernel(
    const float* __restrict__ b2) {
    extern __shared__ float w2s[];   // 2 * CHUNK_FLOATS
    const int tid = threadIdx.x;
    const int warp = tid >> 5, lane = tid & 31;
    const int rbase = blockIdx.x * SP_ROWS + warp * 2;
    const int lane12 = lane * 12;
    const unsigned FULL = 0xffffffffu;

    // prologue: async copy chunk 0
    {
        const float4* src = (const float4*)g_w2t;
        float4* dst = (float4*)w2s;
#pragma unroll
        for (int i = 0; i < 6; i++)
            __pipeline_memcpy_async(dst + tid + i * 1024, src + tid + i * 1024, 16);
        __pipeline_commit();
    }

    const unsigned long long* mrow0 = g_m1 + (size_t)rbase * NCHUNK;
    const unsigned long long* mrow1 = g_m1 + (size_t)(rbase + 1) * NCHUNK;

    float4 a00 = {0,0,0,0}, a01 = {0,0,0,0}, a02 = {0,0,0,0};
    float4 a10 = {0,0,0,0}, a11 = {0,0,0,0}, a12 = {0,0,0,0};

    for (int c = 0; c < NCHUNK; c++) {
        unsigned long long u0 = mrow0[c];
        unsigned long long u1 = mrow1[c];
        __syncthreads();   // all warps done reading buf[(c+1)&1] (chunk c-1)
        if (c + 1 < NCHUNK) {
            const float4* src = (const float4*)(g_w2t + (size_t)(c + 1) * CHUNK_FLOATS);
            float4* dst = (float4*)(w2s + ((c + 1) & 1) * CHUNK_FLOATS);
#pragma unroll
            for (int i = 0; i < 6; i++)
                __pipeline_memcpy_async(dst + tid + i * 1024, src + tid + i * 1024, 16);
            __pipeline_commit();
            __pipeline_wait_prior(1);
        } else {
            __pipeline_wait_prior(0);
        }
        __syncthreads();   // chunk c resident in buf[c&1]

        const float* wbase = w2s + (c & 1) * CHUNK_FLOATS + lane12;
        while (u0 | u1) {
            if (u0) {
                const int j = __ffsll((long long)u0) - 1;
                u0 &= u0 - 1;
                const float4* wr = (const float4*)(wbase + j * Dc);
                const float4 w0 = wr[0], w1 = wr[1], w2v = wr[2];
                ADD_ROW(a00, a01, a02)
            }
            if (u1) {
                const int j = __ffsll((long long)u1) - 1;
                u1 &= u1 - 1;
                const float4* wr = (const float4*)(wbase + j * Dc);
                const float4 w0 = wr[0], w1 = wr[1], w2v = wr[2];
                ADD_ROW(a10, a11, a12)
            }
        }
    }

    // epilogue: bias, store h2, per-row stats
    const float4 bb0 = *(const float4*)(b2 + lane12);
    const float4 bb1 = *(const float4*)(b2 + lane12 + 4);
    const float4 bb2 = *(const float4*)(b2 + lane12 + 8);
#pragma unroll
    for (int rr = 0; rr < 2; rr++) {
        const float4 A0 = rr ? a10 : a00;
        const float4 A1 = rr ? a11 : a01;
        const float4 A2 = rr ? a12 : a02;
        float4 o0, o1, o2;
        o0.x = __fadd_rn(A0.x, bb0.x); o0.y = __fadd_rn(A0.y, bb0.y);
        o0.z = __fadd_rn(A0.z, bb0.z); o0.w = __fadd_rn(A0.w, bb0.w);
        o1.x = __fadd_rn(A1.x, bb1.x); o1.y = __fadd_rn(A1.y, bb1.y);
        o1.z = __fadd_rn(A1.z, bb1.z); o1.w = __fadd_rn(A1.w, bb1.w);
        o2.x = __fadd_rn(A2.x, bb2.x); o2.y = __fadd_rn(A2.y, bb2.y);
        o2.z = __fadd_rn(A2.z, bb2.z); o2.w = __fadd_rn(A2.w, bb2.w);
        const int row = rbase + rr;
        float* q = g_h2 + (size_t)row * Dc + lane12;
        *(float4*)q = o0; *(float4*)(q + 4) = o1; *(float4*)(q + 8) = o2;

        // f32 lane partials, f64 butterfly (same accuracy class as g_p1 path)
        const float sf = P4(o0.x, o0.y, o0.z, o0.w) +
                         P4(o1.x, o1.y, o1.z, o1.w) +
                         P4(o2.x, o2.y, o2.z, o2.w);
        const float qf = P4(o0.x * o0.x, o0.y * o0.y, o0.z * o0.z, o0.w * o0.w) +
                         P4(o1.x * o1.x, o1.y * o1.y, o1.z * o1.z, o1.w * o1.w) +
                         P4(o2.x * o2.x, o2.y * o2.y, o2.z * o2.z, o2.w * o2.w);
        double sd = (double)sf, qd = (double)qf;
#pragma unroll
        for (int o = 16; o; o >>= 1) {
            sd += __shfl_xor_sync(FULL, sd, o);
            qd += __shfl_xor_sync(FULL, qd, o);
        }
        if (lane == 0) {
            const double mu_d = sd / (double)Dc;
            const float var = (float)(qd / (double)Dc - mu_d * mu_d);
            g_st2[row] = make_float2(
                (float)mu_d,
                __fdiv_rn(1.0f, __fsqrt_rn(__fadd_rn(var, 1e-5f))));
        }
    }
}

// ---------------------------------------------------------------------------
// LIF layer 2 -> final output [B,T,L,D]. 384 threads = 4 (b,l) rows x 96
// lanes x float4 (D=384). Stats read from g_st2.
// ---------------------------------------------------------------------------
__global__ __launch_bounds__(384) void lif2_kernel(
    const float* __restrict__ g2, const float* __restrict__ be2,
    float* __restrict__ out) {
    __shared__ float2 st[4][Tc];
    if (threadIdx.x < 16) {
        const int sub_ = threadIdx.x >> 2;
        const int t_ = threadIdx.x & 3;
        const int bl_ = blockIdx.x * 4 + sub_;
        const int r = t_ * (Bc * Lc) + (bl_ / Lc) * Lc + (bl_ % Lc);
        st[sub_][t_] = g_st2[r];
    }
    const int sub = threadIdx.x / 96;        // 0..3
    const int bl = blockIdx.x * 4 + sub;
    const int bI = bl / Lc, l = bl % Lc;
    const int c = (threadIdx.x % 96) * 4;
    const float4 gg = *(const float4*)(g2 + c);
    const float4 bb = *(const float4*)(be2 + c);
    float4 v = {0.f, 0.f, 0.f, 0.f};
    const int rbase = bI * Lc + l;
    __syncthreads();
#pragma unroll
    for (int t = 0; t < Tc; t++) {
        const int r = t * (Bc * Lc) + rbase;
        const size_t off = (size_t)r * Dc + c;
        const float4 y = *(const float4*)(g_h2 + off);
        const float mu = st[sub][t].x, rs = st[sub][t].y;
        float4 sp;
        LIF_STEP(y.x, gg.x, bb.x, v.x, sp.x)
        LIF_STEP(y.y, gg.y, bb.y, v.y, sp.y)
        LIF_STEP(y.z, gg.z, bb.z, v.z, sp.z)
        LIF_STEP(y.w, gg.w, bb.w, v.w, sp.w)
        const size_t oo = (size_t)((bI * Tc + t) * Lc + l) * Dc + c;
        *(float4*)(out + oo) = sp;
    }
}

// ---------------------------------------------------------------------------
extern "C" void kernel_launch(void* const* d_in, const int* in_sizes, int n_in,
                              void* d_out, int out_size) {
    const float* x   = (const float*)d_in[0];
    const float* W1  = (const float*)d_in[1];
    const float* b1  = (const float*)d_in[2];
    const float* g1  = (const float*)d_in[3];
    const float* be1 = (const float*)d_in[4];
    const float* W2  = (const float*)d_in[5];
    const float* b2  = (const float*)d_in[6];
    const float* g2  = (const float*)d_in[7];
    const float* be2 = (const float*)d_in[8];
    float* out = (float*)d_out;

    cudaFuncSetAttribute(spmm2_kernel,
                         cudaFuncAttributeMaxDynamicSharedMemorySize,
                         2 * CHUNK_FLOATS * (int)sizeof(float));

    w2t_kernel<<<dim3(Hc / 32, Dc / 32), dim3(32, 8)>>>(W2);
    gemm1_kernel<<<dim3(Hc / 128, Mrows / 128), 256>>>(x, W1, b1);
    lif1_kernel<<<Bc * Lc, 384>>>(g1, be1);
    spmm2_kernel<<<Mrows / SP_ROWS, SP_THREADS,
                   2 * CHUNK_FLOATS * sizeof(float)>>>(b2);
    lif2_kernel<<<(Bc * Lc) / 4, 384>>>(g2, be2, out);
}